// round 2
// baseline (speedup 1.0000x reference)
#include <cuda_runtime.h>
#include <cstdint>

// ---------------- problem constants ----------------
constexpr int Tn   = 128;   // seq len
constexpr int Bq   = 256;   // batch
constexpr int Hh   = 512;   // hidden
constexpr int Ee   = 16;    // embed
constexpr int Ln   = 4;     // layers
constexpr int G4   = 2048;  // 4H

// ---------------- device scratch (static; no allocation) ----------------
__device__ float d_Wih0[2 * G4 * Ee];           // tf32-rounded copies
__device__ float d_Whh0[2 * G4 * Hh];
__device__ float d_WihL[3 * 2 * G4 * 1024];
__device__ float d_WhhL[3 * 2 * G4 * Hh];
__device__ float d_bias[Ln * 2 * G4];           // bih + bhh
__device__ float d_x0[Tn * Bq * Ee];            // rounded embed[tokens]
__device__ float d_h[2][Ln * 2 * Bq * Hh];      // ping-pong h state
__device__ float d_c[Ln * 2 * Bq * Hh];         // c state (in-place)

// ---------------- helpers ----------------
__device__ __forceinline__ float tf32r(float x) {
    uint32_t u;
    asm("cvt.rna.tf32.f32 %0, %1;" : "=r"(u) : "f"(x));
    return __uint_as_float(u);
}

__device__ __forceinline__ void cp16(float* dst, const float* src) {
    unsigned s = (unsigned)__cvta_generic_to_shared(dst);
    asm volatile("cp.async.cg.shared.global [%0], [%1], 16;\n" :: "r"(s), "l"(src));
}
__device__ __forceinline__ void cp_commit() { asm volatile("cp.async.commit_group;\n"); }
template <int N>
__device__ __forceinline__ void cp_wait() { asm volatile("cp.async.wait_group %0;\n" :: "n"(N)); }

__device__ __forceinline__ void mma_tf32(float* c,
                                         uint32_t a0, uint32_t a1, uint32_t a2, uint32_t a3,
                                         uint32_t b0, uint32_t b1) {
    asm volatile(
        "mma.sync.aligned.m16n8k8.row.col.f32.tf32.tf32.f32 "
        "{%0,%1,%2,%3},{%4,%5,%6,%7},{%8,%9},{%0,%1,%2,%3};\n"
        : "+f"(c[0]), "+f"(c[1]), "+f"(c[2]), "+f"(c[3])
        : "r"(a0), "r"(a1), "r"(a2), "r"(a3), "r"(b0), "r"(b1));
}

__device__ __forceinline__ float sigf(float x) { return 1.0f / (1.0f + __expf(-x)); }

// ---------------- init: round weights to tf32, combine biases, gather x0, zero state ----------------
__global__ void init_kernel(const int* __restrict__ tokens, const float* __restrict__ embed,
                            const float* __restrict__ Wih0, const float* __restrict__ Whh0,
                            const float* __restrict__ bih0, const float* __restrict__ bhh0,
                            const float* __restrict__ Wih,  const float* __restrict__ Whh,
                            const float* __restrict__ bih,  const float* __restrict__ bhh) {
    const int idx0   = blockIdx.x * blockDim.x + threadIdx.x;
    const int stride = gridDim.x * blockDim.x;

    for (int i = idx0; i < 2 * G4 * Ee; i += stride)       d_Wih0[i] = tf32r(Wih0[i]);
    for (int i = idx0; i < 2 * G4 * Hh; i += stride)       d_Whh0[i] = tf32r(Whh0[i]);
    for (int i = idx0; i < 3 * 2 * G4 * 1024; i += stride) d_WihL[i] = tf32r(Wih[i]);
    for (int i = idx0; i < 3 * 2 * G4 * Hh; i += stride)   d_WhhL[i] = tf32r(Whh[i]);

    for (int i = idx0; i < Ln * 2 * G4; i += stride) {
        int l = i / (2 * G4), r = i % (2 * G4);
        d_bias[i] = (l == 0) ? (bih0[r] + bhh0[r])
                             : (bih[(l - 1) * 2 * G4 + r] + bhh[(l - 1) * 2 * G4 + r]);
    }
    for (int i = idx0; i < Tn * Bq * Ee; i += stride) {
        int t = i / (Bq * Ee);
        int rem = i % (Bq * Ee);
        int b = rem / Ee, e = rem % Ee;
        d_x0[i] = tf32r(embed[tokens[t * Bq + b] * Ee + e]);
    }
    for (int i = idx0; i < Ln * 2 * Bq * Hh; i += stride) {
        d_h[0][i] = 0.f;
        d_c[i]    = 0.f;
    }
}

// ---------------- fused LSTM layer-step ----------------
// Per block: 64 batch rows x 32 hidden units (=128 gate columns: i,f,g,o slices).
// GEMM: C[64,128] = X[64,KIN]*Wih^T + Hprev[64,512]*Whh^T (K concatenated).
// grid = (4 mtiles, 16 jtiles, 2 dirs), 256 threads (8 warps, 32x32 warp tiles).
template <int KIN>
__global__ __launch_bounds__(256) void lstm_step(int t, int l) {
    constexpr int NIT = (KIN + Hh) / 16;
    __shared__ __align__(16) float smem[8512];   // sA[2][64][20] | sB[2][128][20]; reused as gtile[64][133]
    float* sA = smem;          // 2560 floats
    float* sB = smem + 2560;   // 5120 floats

    const int tid = threadIdx.x;
    const int mt  = blockIdx.x;   // 0..3
    const int jt  = blockIdx.y;   // 0..15
    const int dir = blockIdx.z;   // 0..1
    const int b0  = mt * 64, j0 = jt * 32;

    const int rb = t & 1, wb = (t + 1) & 1;
    const float* __restrict__ hprevD = d_h[rb] + (l * 2 + dir) * Bq * Hh;
    float* __restrict__       houtD  = d_h[wb] + (l * 2 + dir) * Bq * Hh;
    float* __restrict__       cstD   = d_c     + (l * 2 + dir) * Bq * Hh;
    const float* __restrict__ xbase  = (KIN == Ee) ? (d_x0 + t * Bq * Ee)
                                                   : (d_h[wb] + (l - 1) * 2 * Bq * Hh);
    const float* __restrict__ WihD   = (KIN == Ee) ? (d_Wih0 + dir * G4 * Ee)
                                                   : (d_WihL + ((l - 1) * 2 + dir) * G4 * 1024);
    const float* __restrict__ WhhD   = (KIN == Ee) ? (d_Whh0 + dir * G4 * Hh)
                                                   : (d_WhhL + ((l - 1) * 2 + dir) * G4 * Hh);

    const int arow = tid >> 2, acol = (tid & 3) * 4;
    const int abg  = b0 + arow;

    auto load_stage = [&](int it, int buf) {
        const int k0 = it * 16;
        {   // A tile: 64 x 16
            int kk = k0 + acol;
            const float* src;
            if (kk < KIN) {
                if (KIN == Ee) src = xbase + abg * Ee + kk;
                else           src = xbase + ((kk >> 9) * Bq + abg) * Hh + (kk & 511);
            } else {
                src = hprevD + abg * Hh + (kk - KIN);
            }
            cp16(&sA[buf * 1280 + arow * 20 + acol], src);
        }
        // B tile: 128 x 16 (rows are gate*512 + j0 + n%32)
        #pragma unroll
        for (int q = 0; q < 2; ++q) {
            int ch = tid + q * 256;
            int n = ch >> 2, cc = (ch & 3) * 4;
            int wrow = (n >> 5) * Hh + j0 + (n & 31);
            int kk = k0 + cc;
            const float* src = (kk < KIN) ? (WihD + wrow * KIN + kk)
                                          : (WhhD + wrow * Hh + (kk - KIN));
            cp16(&sB[buf * 2560 + n * 20 + cc], src);
        }
        cp_commit();
    };

    const int lane = tid & 31, wid = tid >> 5;
    const int wm = wid & 1, wn = wid >> 1;     // 32-row x 32-col warp tile
    const int g = lane >> 2, tg = lane & 3;

    float acc[2][4][4];
    #pragma unroll
    for (int i = 0; i < 2; i++)
        #pragma unroll
        for (int j = 0; j < 4; j++)
            #pragma unroll
            for (int k = 0; k < 4; k++) acc[i][j][k] = 0.f;

    load_stage(0, 0);
    for (int it = 0; it < NIT; ++it) {
        if (it + 1 < NIT) { load_stage(it + 1, (it + 1) & 1); cp_wait<1>(); }
        else              { cp_wait<0>(); }
        __syncthreads();
        const float* A  = sA + (it & 1) * 1280;
        const float* Bs = sB + (it & 1) * 2560;
        #pragma unroll
        for (int kc = 0; kc < 16; kc += 8) {
            uint32_t a[2][4];
            #pragma unroll
            for (int mi = 0; mi < 2; ++mi) {
                int r = wm * 32 + mi * 16 + g;
                a[mi][0] = __float_as_uint(A[r * 20 + kc + tg]);
                a[mi][1] = __float_as_uint(A[(r + 8) * 20 + kc + tg]);
                a[mi][2] = __float_as_uint(A[r * 20 + kc + tg + 4]);
                a[mi][3] = __float_as_uint(A[(r + 8) * 20 + kc + tg + 4]);
            }
            #pragma unroll
            for (int ni = 0; ni < 4; ++ni) {
                int n = wn * 32 + ni * 8 + g;
                uint32_t b0r = __float_as_uint(Bs[n * 20 + kc + tg]);
                uint32_t b1r = __float_as_uint(Bs[n * 20 + kc + tg + 4]);
                mma_tf32(acc[0][ni], a[0][0], a[0][1], a[0][2], a[0][3], b0r, b1r);
                mma_tf32(acc[1][ni], a[1][0], a[1][1], a[1][2], a[1][3], b0r, b1r);
            }
        }
        __syncthreads();
    }

    // stage gate tile to smem (stride 133 to kill bank conflicts)
    float* gt = smem;
    #pragma unroll
    for (int mi = 0; mi < 2; ++mi)
        #pragma unroll
        for (int ni = 0; ni < 4; ++ni) {
            int r = wm * 32 + mi * 16 + g;
            int cc = wn * 32 + ni * 8 + 2 * tg;
            gt[r * 133 + cc]           = acc[mi][ni][0];
            gt[r * 133 + cc + 1]       = acc[mi][ni][1];
            gt[(r + 8) * 133 + cc]     = acc[mi][ni][2];
            gt[(r + 8) * 133 + cc + 1] = acc[mi][ni][3];
        }
    __syncthreads();

    // elementwise LSTM cell update: 64 rows x 32 units, 8 cells/thread, coalesced over jj
    const int jj = tid & 31;
    const int rbase = tid >> 5;
    const float* biasD = d_bias + (l * 2 + dir) * G4;
    const int j = j0 + jj;
    const float bi = biasD[0 * Hh + j];
    const float bf = biasD[1 * Hh + j];
    const float bg = biasD[2 * Hh + j];
    const float bo = biasD[3 * Hh + j];
    #pragma unroll
    for (int q = 0; q < 8; ++q) {
        int row = rbase + q * 8;
        int b = b0 + row;
        float gi = gt[row * 133 + jj]      + bi;
        float gf = gt[row * 133 + 32 + jj] + bf;
        float gg = gt[row * 133 + 64 + jj] + bg;
        float go = gt[row * 133 + 96 + jj] + bo;
        float i_ = sigf(gi), f_ = sigf(gf), g_ = tanhf(gg), o_ = sigf(go);
        int idx = b * Hh + j;
        float cn = fmaf(f_, cstD[idx], i_ * g_);
        cstD[idx]  = cn;
        houtD[idx] = tf32r(o_ * tanhf(cn));   // h feeds tf32 GEMMs: pre-round (rna, unbiased)
    }
}

// ---------------- final FC + softmax ----------------
// hid[b, s*1024 + (j | 512+j)] = (h | c)[s, b, j], s = l*2+d; out = softmax(hid @ fc_w^T + fc_b)
__global__ __launch_bounds__(256) void fc_softmax(const float* __restrict__ fcw,
                                                  const float* __restrict__ fcb,
                                                  float* __restrict__ out) {
    const int b = blockIdx.x;
    const int tid = threadIdx.x, lane = tid & 31, w = tid >> 5;
    __shared__ float sv[64];
    const float* __restrict__ hf = d_h[0];   // t=127 writes buffer 0
    float acc[8] = {0, 0, 0, 0, 0, 0, 0, 0};
    for (int k = lane; k < 8192; k += 32) {
        int s = k >> 10, r = k & 1023;
        float hv = (r & 512) ? d_c[(s * Bq + b) * Hh + (r & 511)]
                             : hf[(s * Bq + b) * Hh + (r & 511)];
        #pragma unroll
        for (int q = 0; q < 8; ++q)
            acc[q] = fmaf(hv, fcw[(w * 8 + q) * 8192 + k], acc[q]);
    }
    #pragma unroll
    for (int q = 0; q < 8; ++q) {
        float v = acc[q];
        #pragma unroll
        for (int off = 16; off; off >>= 1) v += __shfl_xor_sync(0xffffffffu, v, off);
        if (lane == 0) sv[w * 8 + q] = v + fcb[w * 8 + q];
    }
    __syncthreads();
    if (tid < 32) {
        float v0 = sv[tid], v1 = sv[tid + 32];
        float m = fmaxf(v0, v1);
        #pragma unroll
        for (int off = 16; off; off >>= 1) m = fmaxf(m, __shfl_xor_sync(0xffffffffu, m, off));
        float e0 = expf(v0 - m), e1 = expf(v1 - m);
        float s = e0 + e1;
        #pragma unroll
        for (int off = 16; off; off >>= 1) s += __shfl_xor_sync(0xffffffffu, s, off);
        float inv = 1.0f / s;
        out[b * 64 + tid]      = e0 * inv;
        out[b * 64 + 32 + tid] = e1 * inv;
    }
}

// ---------------- launch ----------------
extern "C" void kernel_launch(void* const* d_in, const int* in_sizes, int n_in,
                              void* d_out, int out_size) {
    const int*   tokens = (const int*)  d_in[0];
    const float* embed  = (const float*)d_in[1];
    const float* Wih0   = (const float*)d_in[2];
    const float* Whh0   = (const float*)d_in[3];
    const float* bih0   = (const float*)d_in[4];
    const float* bhh0   = (const float*)d_in[5];
    const float* Wih    = (const float*)d_in[6];
    const float* Whh    = (const float*)d_in[7];
    const float* bih    = (const float*)d_in[8];
    const float* bhh    = (const float*)d_in[9];
    const float* fcw    = (const float*)d_in[10];
    const float* fcb    = (const float*)d_in[11];
    float*       out    = (float*)d_out;

    init_kernel<<<512, 256>>>(tokens, embed, Wih0, Whh0, bih0, bhh0, Wih, Whh, bih, bhh);

    dim3 grid(4, 16, 2);
    for (int t = 0; t < Tn; ++t) {
        lstm_step<Ee><<<grid, 256>>>(t, 0);
        for (int l = 1; l < Ln; ++l)
            lstm_step<1024><<<grid, 256>>>(t, l);
    }
    fc_softmax<<<Bq, 256>>>(fcw, fcb, out);
}

// round 3
// speedup vs baseline: 2.2807x; 2.2807x over previous
#include <cuda_runtime.h>
#include <cstdint>

// ---------------- problem constants ----------------
constexpr int Tn   = 128;   // seq len
constexpr int Bq   = 256;   // batch
constexpr int Hh   = 512;   // hidden
constexpr int Ee   = 16;    // embed
constexpr int Ln   = 4;     // layers
constexpr int G4   = 2048;  // 4H

// ---------------- device scratch (static; no allocation) ----------------
__device__ float d_Wih0[2 * G4 * Ee];           // tf32-rounded copies
__device__ float d_Whh0[2 * G4 * Hh];
__device__ float d_WihL[3 * 2 * G4 * 1024];
__device__ float d_WhhL[3 * 2 * G4 * Hh];
__device__ float d_bias[Ln * 2 * G4];           // bih + bhh
__device__ float d_x0[Tn * Bq * Ee];            // rounded embed[tokens]
__device__ float d_h[3][Ln * 2 * Bq * Hh];      // 3-deep ring of h state (wavefront-safe)
__device__ float d_c[Ln * 2 * Bq * Hh];         // c state (in-place)

// ---------------- helpers ----------------
__device__ __forceinline__ float tf32r(float x) {
    uint32_t u;
    asm("cvt.rna.tf32.f32 %0, %1;" : "=r"(u) : "f"(x));
    return __uint_as_float(u);
}

__device__ __forceinline__ void cp16(float* dst, const float* src) {
    unsigned s = (unsigned)__cvta_generic_to_shared(dst);
    asm volatile("cp.async.cg.shared.global [%0], [%1], 16;\n" :: "r"(s), "l"(src));
}
__device__ __forceinline__ void cp_commit() { asm volatile("cp.async.commit_group;\n"); }
template <int N>
__device__ __forceinline__ void cp_wait() { asm volatile("cp.async.wait_group %0;\n" :: "n"(N)); }

__device__ __forceinline__ void mma_tf32(float* c,
                                         uint32_t a0, uint32_t a1, uint32_t a2, uint32_t a3,
                                         uint32_t b0, uint32_t b1) {
    asm volatile(
        "mma.sync.aligned.m16n8k8.row.col.f32.tf32.tf32.f32 "
        "{%0,%1,%2,%3},{%4,%5,%6,%7},{%8,%9},{%0,%1,%2,%3};\n"
        : "+f"(c[0]), "+f"(c[1]), "+f"(c[2]), "+f"(c[3])
        : "r"(a0), "r"(a1), "r"(a2), "r"(a3), "r"(b0), "r"(b1));
}

__device__ __forceinline__ float sigf(float x) { return 1.0f / (1.0f + __expf(-x)); }

// ---------------- init ----------------
__global__ void init_kernel(const int* __restrict__ tokens, const float* __restrict__ embed,
                            const float* __restrict__ Wih0, const float* __restrict__ Whh0,
                            const float* __restrict__ bih0, const float* __restrict__ bhh0,
                            const float* __restrict__ Wih,  const float* __restrict__ Whh,
                            const float* __restrict__ bih,  const float* __restrict__ bhh) {
    const int idx0   = blockIdx.x * blockDim.x + threadIdx.x;
    const int stride = gridDim.x * blockDim.x;

    for (int i = idx0; i < 2 * G4 * Ee; i += stride)       d_Wih0[i] = tf32r(Wih0[i]);
    for (int i = idx0; i < 2 * G4 * Hh; i += stride)       d_Whh0[i] = tf32r(Whh0[i]);
    for (int i = idx0; i < 3 * 2 * G4 * 1024; i += stride) d_WihL[i] = tf32r(Wih[i]);
    for (int i = idx0; i < 3 * 2 * G4 * Hh; i += stride)   d_WhhL[i] = tf32r(Whh[i]);

    for (int i = idx0; i < Ln * 2 * G4; i += stride) {
        int l = i / (2 * G4), r = i % (2 * G4);
        d_bias[i] = (l == 0) ? (bih0[r] + bhh0[r])
                             : (bih[(l - 1) * 2 * G4 + r] + bhh[(l - 1) * 2 * G4 + r]);
    }
    for (int i = idx0; i < Tn * Bq * Ee; i += stride) {
        int t = i / (Bq * Ee);
        int rem = i % (Bq * Ee);
        int b = rem / Ee, e = rem % Ee;
        d_x0[i] = tf32r(embed[tokens[t * Bq + b] * Ee + e]);
    }
    for (int i = idx0; i < Ln * 2 * Bq * Hh; i += stride) {
        d_h[0][i] = 0.f;
        d_h[1][i] = 0.f;
        d_h[2][i] = 0.f;   // t=0 reads hprev from ring slot 2 -> must be zero
        d_c[i]    = 0.f;
    }
}

// ---------------- one LSTM cell (t, l, dir): 64 batch x 32 hidden per block ----------------
// Ring-buffer contract: cell (t,l) writes h into d_h[t%3]; reads hprev from d_h[(t+2)%3];
// reads x (l>0) from d_h[t%3] slot l-1 (written by (t,l-1) in an earlier wavefront).
template <int KIN>
__device__ __forceinline__ void lstm_cell(int t, int l, int dir, float* smem) {
    constexpr int NIT = (KIN + Hh) / 16;
    float* sA = smem;          // [2][64][20]  = 2560 floats
    float* sB = smem + 2560;   // [2][128][20] = 5120 floats

    const int tid = threadIdx.x;
    const int mt  = blockIdx.x;   // 0..3
    const int jt  = blockIdx.y;   // 0..15
    const int b0  = mt * 64, j0 = jt * 32;

    const int rb = (t + 2) % 3, wb = t % 3;
    const float* __restrict__ hprevD = d_h[rb] + (l * 2 + dir) * Bq * Hh;
    float* __restrict__       houtD  = d_h[wb] + (l * 2 + dir) * Bq * Hh;
    float* __restrict__       cstD   = d_c     + (l * 2 + dir) * Bq * Hh;
    const float* __restrict__ xbase  = (KIN == Ee) ? (d_x0 + t * Bq * Ee)
                                                   : (d_h[wb] + (l - 1) * 2 * Bq * Hh);
    const float* __restrict__ WihD   = (KIN == Ee) ? (d_Wih0 + dir * G4 * Ee)
                                                   : (d_WihL + ((l - 1) * 2 + dir) * G4 * 1024);
    const float* __restrict__ WhhD   = (KIN == Ee) ? (d_Whh0 + dir * G4 * Hh)
                                                   : (d_WhhL + ((l - 1) * 2 + dir) * G4 * Hh);

    const int arow = tid >> 2, acol = (tid & 3) * 4;
    const int abg  = b0 + arow;

    auto load_stage = [&](int it, int buf) {
        const int k0 = it * 16;
        {   // A tile: 64 x 16
            int kk = k0 + acol;
            const float* src;
            if (kk < KIN) {
                if (KIN == Ee) src = xbase + abg * Ee + kk;
                else           src = xbase + ((kk >> 9) * Bq + abg) * Hh + (kk & 511);
            } else {
                src = hprevD + abg * Hh + (kk - KIN);
            }
            cp16(&sA[buf * 1280 + arow * 20 + acol], src);
        }
        // B tile: 128 x 16 (rows are gate*512 + j0 + n%32)
        #pragma unroll
        for (int q = 0; q < 2; ++q) {
            int ch = tid + q * 256;
            int n = ch >> 2, cc = (ch & 3) * 4;
            int wrow = (n >> 5) * Hh + j0 + (n & 31);
            int kk = k0 + cc;
            const float* src = (kk < KIN) ? (WihD + wrow * KIN + kk)
                                          : (WhhD + wrow * Hh + (kk - KIN));
            cp16(&sB[buf * 2560 + n * 20 + cc], src);
        }
        cp_commit();
    };

    const int lane = tid & 31, wid = tid >> 5;
    const int wm = wid & 1, wn = wid >> 1;     // 32-row x 32-col warp tile
    const int g = lane >> 2, tg = lane & 3;

    float acc[2][4][4];
    #pragma unroll
    for (int i = 0; i < 2; i++)
        #pragma unroll
        for (int j = 0; j < 4; j++)
            #pragma unroll
            for (int k = 0; k < 4; k++) acc[i][j][k] = 0.f;

    load_stage(0, 0);
    for (int it = 0; it < NIT; ++it) {
        if (it + 1 < NIT) { load_stage(it + 1, (it + 1) & 1); cp_wait<1>(); }
        else              { cp_wait<0>(); }
        __syncthreads();
        const float* A  = sA + (it & 1) * 1280;
        const float* Bs = sB + (it & 1) * 2560;
        #pragma unroll
        for (int kc = 0; kc < 16; kc += 8) {
            uint32_t a[2][4];
            #pragma unroll
            for (int mi = 0; mi < 2; ++mi) {
                int r = wm * 32 + mi * 16 + g;
                a[mi][0] = __float_as_uint(A[r * 20 + kc + tg]);
                a[mi][1] = __float_as_uint(A[(r + 8) * 20 + kc + tg]);
                a[mi][2] = __float_as_uint(A[r * 20 + kc + tg + 4]);
                a[mi][3] = __float_as_uint(A[(r + 8) * 20 + kc + tg + 4]);
            }
            #pragma unroll
            for (int ni = 0; ni < 4; ++ni) {
                int n = wn * 32 + ni * 8 + g;
                uint32_t b0r = __float_as_uint(Bs[n * 20 + kc + tg]);
                uint32_t b1r = __float_as_uint(Bs[n * 20 + kc + tg + 4]);
                mma_tf32(acc[0][ni], a[0][0], a[0][1], a[0][2], a[0][3], b0r, b1r);
                mma_tf32(acc[1][ni], a[1][0], a[1][1], a[1][2], a[1][3], b0r, b1r);
            }
        }
        __syncthreads();
    }

    // stage gate tile to smem (stride 133 to kill bank conflicts)
    float* gt = smem;
    #pragma unroll
    for (int mi = 0; mi < 2; ++mi)
        #pragma unroll
        for (int ni = 0; ni < 4; ++ni) {
            int r = wm * 32 + mi * 16 + g;
            int cc = wn * 32 + ni * 8 + 2 * tg;
            gt[r * 133 + cc]           = acc[mi][ni][0];
            gt[r * 133 + cc + 1]       = acc[mi][ni][1];
            gt[(r + 8) * 133 + cc]     = acc[mi][ni][2];
            gt[(r + 8) * 133 + cc + 1] = acc[mi][ni][3];
        }
    __syncthreads();

    // elementwise LSTM cell update: 64 rows x 32 units, 8 cells/thread
    const int jj = tid & 31;
    const int rbase = tid >> 5;
    const float* biasD = d_bias + (l * 2 + dir) * G4;
    const int j = j0 + jj;
    const float bi = biasD[0 * Hh + j];
    const float bf = biasD[1 * Hh + j];
    const float bg = biasD[2 * Hh + j];
    const float bo = biasD[3 * Hh + j];
    #pragma unroll
    for (int q = 0; q < 8; ++q) {
        int row = rbase + q * 8;
        int b = b0 + row;
        float gi = gt[row * 133 + jj]      + bi;
        float gf = gt[row * 133 + 32 + jj] + bf;
        float gg = gt[row * 133 + 64 + jj] + bg;
        float go = gt[row * 133 + 96 + jj] + bo;
        float i_ = sigf(gi), f_ = sigf(gf), g_ = tanhf(gg), o_ = sigf(go);
        int idx = b * Hh + j;
        float cn = fmaf(f_, cstD[idx], i_ * g_);
        cstD[idx]  = cn;
        houtD[idx] = tf32r(o_ * tanhf(cn));   // h feeds tf32 GEMMs: pre-round (rna)
    }
}

// ---------------- wavefront kernel: all independent (t,l) cells of one anti-diagonal ----------------
// grid = (4 mtiles, 16 jtiles, ncells*2); blockIdx.z = (cell_idx << 1) | dir
__global__ __launch_bounds__(256, 3) void lstm_wave(int w, int lmin) {
    __shared__ __align__(16) float smem[8512];
    const int cell = blockIdx.z >> 1;
    const int dir  = blockIdx.z & 1;
    const int l    = lmin + cell;
    const int t    = w - l;
    if (t < 0 || t >= Tn) return;
    if (l == 0) lstm_cell<Ee>(t, 0, dir, smem);
    else        lstm_cell<1024>(t, l, dir, smem);
}

// ---------------- final FC + softmax ----------------
__global__ __launch_bounds__(256) void fc_softmax(const float* __restrict__ fcw,
                                                  const float* __restrict__ fcb,
                                                  float* __restrict__ out) {
    const int b = blockIdx.x;
    const int tid = threadIdx.x, lane = tid & 31, w = tid >> 5;
    __shared__ float sv[64];
    const float* __restrict__ hf = d_h[(Tn - 1) % 3];   // t=127 wrote ring slot 1
    float acc[8] = {0, 0, 0, 0, 0, 0, 0, 0};
    for (int k = lane; k < 8192; k += 32) {
        int s = k >> 10, r = k & 1023;
        float hv = (r & 512) ? d_c[(s * Bq + b) * Hh + (r & 511)]
                             : hf[(s * Bq + b) * Hh + (r & 511)];
        #pragma unroll
        for (int q = 0; q < 8; ++q)
            acc[q] = fmaf(hv, fcw[(w * 8 + q) * 8192 + k], acc[q]);
    }
    #pragma unroll
    for (int q = 0; q < 8; ++q) {
        float v = acc[q];
        #pragma unroll
        for (int off = 16; off; off >>= 1) v += __shfl_xor_sync(0xffffffffu, v, off);
        if (lane == 0) sv[w * 8 + q] = v + fcb[w * 8 + q];
    }
    __syncthreads();
    if (tid < 32) {
        float v0 = sv[tid], v1 = sv[tid + 32];
        float m = fmaxf(v0, v1);
        #pragma unroll
        for (int off = 16; off; off >>= 1) m = fmaxf(m, __shfl_xor_sync(0xffffffffu, m, off));
        float e0 = expf(v0 - m), e1 = expf(v1 - m);
        float s = e0 + e1;
        #pragma unroll
        for (int off = 16; off; off >>= 1) s += __shfl_xor_sync(0xffffffffu, s, off);
        float inv = 1.0f / s;
        out[b * 64 + tid]      = e0 * inv;
        out[b * 64 + 32 + tid] = e1 * inv;
    }
}

// ---------------- launch ----------------
extern "C" void kernel_launch(void* const* d_in, const int* in_sizes, int n_in,
                              void* d_out, int out_size) {
    const int*   tokens = (const int*)  d_in[0];
    const float* embed  = (const float*)d_in[1];
    const float* Wih0   = (const float*)d_in[2];
    const float* Whh0   = (const float*)d_in[3];
    const float* bih0   = (const float*)d_in[4];
    const float* bhh0   = (const float*)d_in[5];
    const float* Wih    = (const float*)d_in[6];
    const float* Whh    = (const float*)d_in[7];
    const float* bih    = (const float*)d_in[8];
    const float* bhh    = (const float*)d_in[9];
    const float* fcw    = (const float*)d_in[10];
    const float* fcb    = (const float*)d_in[11];
    float*       out    = (float*)d_out;

    init_kernel<<<512, 256>>>(tokens, embed, Wih0, Whh0, bih0, bhh0, Wih, Whh, bih, bhh);

    // wavefront schedule: cells (t, l) with t + l == w are independent
    for (int w = 0; w <= (Tn - 1) + (Ln - 1); ++w) {
        int lmin = max(0, w - (Tn - 1));
        int lmax = min(Ln - 1, w);
        int ncells = lmax - lmin + 1;
        dim3 grid(4, 16, ncells * 2);
        lstm_wave<<<grid, 256>>>(w, lmin);
    }
    fc_softmax<<<Bq, 256>>>(fcw, fcb, out);
}